// round 2
// baseline (speedup 1.0000x reference)
#include <cuda_runtime.h>
#include <cstdint>
#include <cstddef>

#define B_DIM 64
#define S_DIM 512
#define E_DIM 256
#define D_DIM 512

// Combined conv weights, layout [tap][D][E]
__device__ float g_Wc [6 * D_DIM * E_DIM];   // interior, taps delta = -2..3
__device__ float g_Wc1[5 * D_DIM * E_DIM];   // i == 1,  taps delta = -1..3
__device__ float g_Wc0[4 * D_DIM * E_DIM];   // i == 0,  taps delta =  0..3
__device__ float g_bias[3 * D_DIM];          // [class0, class1, interior]

// ---------------------------------------------------------------------------
// Preprocessing: build combined weights from W1..W4.
// Interior (i>=2): y[i] = sum_delta C_delta x_{i+delta}, where
//   contributions: n-gram n (>=2) contributes W_n[:,:,k] for window shift
//   j in [0, n-2] with delta = k - j. n=1 contributes at delta=0.
// ---------------------------------------------------------------------------
__global__ void preproc_kernel(
    const float* __restrict__ W1, const float* __restrict__ b1,
    const float* __restrict__ W2, const float* __restrict__ b2,
    const float* __restrict__ W3, const float* __restrict__ b3,
    const float* __restrict__ W4, const float* __restrict__ b4)
{
    int idx = blockIdx.x * blockDim.x + threadIdx.x;
    if (idx >= D_DIM * E_DIM) return;
    int d = idx >> 8;   // / E_DIM
    int e = idx & 255;
    (void)e;

    float w1  = W1[idx];
    const float* p2 = W2 + (size_t)idx * 2;
    float w20 = p2[0], w21 = p2[1];
    const float* p3 = W3 + (size_t)idx * 3;
    float w30 = p3[0], w31 = p3[1], w32 = p3[2];
    const float* p4 = W4 + (size_t)idx * 4;
    float w40 = p4[0], w41 = p4[1], w42 = p4[2], w43 = p4[3];

    const size_t st = (size_t)D_DIM * E_DIM;
    // interior: delta = t - 2
    g_Wc[0 * st + idx] = w40;                                        // d=-2: (4,j2,k0)
    g_Wc[1 * st + idx] = w30 + w40 + w41;                            // d=-1
    g_Wc[2 * st + idx] = w1 + w20 + w30 + w31 + w40 + w41 + w42;     // d=0
    g_Wc[3 * st + idx] = w21 + w31 + w32 + w41 + w42 + w43;          // d=1
    g_Wc[4 * st + idx] = w32 + w42 + w43;                            // d=2
    g_Wc[5 * st + idx] = w43;                                        // d=3
    // class i==1: j <= min(n-2,1), delta = t - 1
    g_Wc1[0 * st + idx] = w30 + w40;
    g_Wc1[1 * st + idx] = w1 + w20 + w30 + w31 + w40 + w41;
    g_Wc1[2 * st + idx] = w21 + w31 + w32 + w41 + w42;
    g_Wc1[3 * st + idx] = w32 + w42 + w43;
    g_Wc1[4 * st + idx] = w43;
    // class i==0: j == 0 only, delta = t
    g_Wc0[0 * st + idx] = w1 + w20 + w30 + w40;
    g_Wc0[1 * st + idx] = w21 + w31 + w41;
    g_Wc0[2 * st + idx] = w32 + w42;
    g_Wc0[3 * st + idx] = w43;

    if (e == 0) {
        float B1 = b1[d], B2 = b2[d], B3 = b3[d], B4 = b4[d];
        g_bias[0 * D_DIM + d] = B1 + B2 + B3 + B4;                   // i==0
        g_bias[1 * D_DIM + d] = B1 + B2 + 2.f * B3 + 2.f * B4;       // i==1
        g_bias[2 * D_DIM + d] = B1 + B2 + 2.f * B3 + 3.f * B4;       // interior
    }
}

// ---------------------------------------------------------------------------
// Tap-conv GEMM: y[b, i, d] = bias[d] + sum_t sum_e W[t][d][e] * x[b, i+delta0+t, e]
// Rows r = b * i_count + (i - i_begin), tiled 64 rows x 64 d-cols per block,
// 256 threads, 4x4 microtile per thread, K chunked by (tap, 64-e slice).
// ---------------------------------------------------------------------------
__global__ void __launch_bounds__(256) conv_gemm_kernel(
    const float* __restrict__ x,      // [B, S, E]
    const float* __restrict__ W,      // [T, D, E]
    const float* __restrict__ bias,   // [D]
    float* __restrict__ out,          // [B, S, D]
    int T, int delta0, int i_begin, int i_count)
{
    __shared__ float Xs[64][68];   // [e][m], padded
    __shared__ float Ws[64][68];   // [e][n], padded

    const int tid = threadIdx.x;
    const int tx = tid & 15;       // n-group (4 cols each)
    const int ty = tid >> 4;       // m-group (4 rows each)
    const int rowTile = blockIdx.x * 64;
    const int d0 = blockIdx.y * 64;

    const int le  = tid & 63;      // e within chunk (loader)
    const int lm0 = tid >> 6;      // 0..3 (loader row phase)

    // Precompute global row bases (b*S + i) for the 16 rows this thread loads.
    int rbase[16];
#pragma unroll
    for (int j = 0; j < 16; ++j) {
        int r = rowTile + lm0 + 4 * j;
        int b = r / i_count;
        int i = i_begin + (r - b * i_count);
        rbase[j] = b * S_DIM + i;
    }

    float acc[4][4];
#pragma unroll
    for (int a = 0; a < 4; ++a)
#pragma unroll
        for (int c = 0; c < 4; ++c) acc[a][c] = 0.f;

    for (int t = 0; t < T; ++t) {
        const float* Wt = W + ((size_t)t * D_DIM + d0) * E_DIM;
        const int xoff = delta0 + t;
        for (int ec = 0; ec < E_DIM; ec += 64) {
#pragma unroll
            for (int j = 0; j < 16; ++j) {
                Xs[le][lm0 + 4 * j] =
                    x[(size_t)(rbase[j] + xoff) * E_DIM + ec + le];
            }
#pragma unroll
            for (int j = 0; j < 16; ++j) {
                Ws[le][lm0 + 4 * j] = Wt[(size_t)(lm0 + 4 * j) * E_DIM + ec + le];
            }
            __syncthreads();
#pragma unroll 16
            for (int e = 0; e < 64; ++e) {
                float4 av = *reinterpret_cast<const float4*>(&Xs[e][ty * 4]);
                float4 bv = *reinterpret_cast<const float4*>(&Ws[e][tx * 4]);
                acc[0][0] += av.x * bv.x; acc[0][1] += av.x * bv.y;
                acc[0][2] += av.x * bv.z; acc[0][3] += av.x * bv.w;
                acc[1][0] += av.y * bv.x; acc[1][1] += av.y * bv.y;
                acc[1][2] += av.y * bv.z; acc[1][3] += av.y * bv.w;
                acc[2][0] += av.z * bv.x; acc[2][1] += av.z * bv.y;
                acc[2][2] += av.z * bv.z; acc[2][3] += av.z * bv.w;
                acc[3][0] += av.w * bv.x; acc[3][1] += av.w * bv.y;
                acc[3][2] += av.w * bv.z; acc[3][3] += av.w * bv.w;
            }
            __syncthreads();
        }
    }

    float bs0 = bias[d0 + tx * 4 + 0];
    float bs1 = bias[d0 + tx * 4 + 1];
    float bs2 = bias[d0 + tx * 4 + 2];
    float bs3 = bias[d0 + tx * 4 + 3];

#pragma unroll
    for (int mr = 0; mr < 4; ++mr) {
        int r = rowTile + ty * 4 + mr;
        int b = r / i_count;
        int i = i_begin + (r - b * i_count);
        float4 o;
        o.x = acc[mr][0] + bs0;
        o.y = acc[mr][1] + bs1;
        o.z = acc[mr][2] + bs2;
        o.w = acc[mr][3] + bs3;
        *reinterpret_cast<float4*>(
            &out[((size_t)(b * S_DIM + i)) * D_DIM + d0 + tx * 4]) = o;
    }
}

extern "C" void kernel_launch(void* const* d_in, const int* in_sizes, int n_in,
                              void* d_out, int out_size)
{
    (void)in_sizes; (void)n_in; (void)out_size;
    const float* x  = (const float*)d_in[0];
    const float* W1 = (const float*)d_in[1];
    const float* b1 = (const float*)d_in[2];
    const float* W2 = (const float*)d_in[3];
    const float* b2 = (const float*)d_in[4];
    const float* W3 = (const float*)d_in[5];
    const float* b3 = (const float*)d_in[6];
    const float* W4 = (const float*)d_in[7];
    const float* b4 = (const float*)d_in[8];
    float* out = (float*)d_out;

    float *pWc, *pWc1, *pWc0, *pBias;
    cudaGetSymbolAddress((void**)&pWc,  g_Wc);
    cudaGetSymbolAddress((void**)&pWc1, g_Wc1);
    cudaGetSymbolAddress((void**)&pWc0, g_Wc0);
    cudaGetSymbolAddress((void**)&pBias, g_bias);

    // 1) Build combined weights (tiny)
    preproc_kernel<<<(D_DIM * E_DIM + 255) / 256, 256>>>(W1, b1, W2, b2, W3, b3, W4, b4);

    // 2) Boundary rows i=0 (4 taps) and i=1 (5 taps): 64 rows each
    conv_gemm_kernel<<<dim3(1, D_DIM / 64), 256>>>(x, pWc0, pBias + 0 * D_DIM, out, 4,  0, 0, 1);
    conv_gemm_kernel<<<dim3(1, D_DIM / 64), 256>>>(x, pWc1, pBias + 1 * D_DIM, out, 5, -1, 1, 1);

    // 3) Interior rows i in [2, 256): 6-tap combined conv (64*254 rows)
    conv_gemm_kernel<<<dim3((B_DIM * 254) / 64, D_DIM / 64), 256>>>(
        x, pWc, pBias + 2 * D_DIM, out, 6, -2, 2, 254);

    // 4) Tail rows i in [256, 512): unigram only, W1 is already [1][D][E]
    conv_gemm_kernel<<<dim3((B_DIM * 256) / 64, D_DIM / 64), 256>>>(
        x, W1, b1, out, 1, 0, 256, 256);
}

// round 5
// speedup vs baseline: 3.0974x; 3.0974x over previous
#include <cuda_runtime.h>
#include <cuda_bf16.h>
#include <cstdint>
#include <cstddef>

#define BB 64
#define SEQ 512
#define EE 256
#define DDIM 512
#define NTAPS 16
#define DE (DDIM * EE)

// device scratch (no allocations allowed)
__device__ __align__(16) __nv_bfloat16 g_Whi[NTAPS * DE];
__device__ __align__(16) __nv_bfloat16 g_Wlo[NTAPS * DE];
__device__ __align__(16) __nv_bfloat16 g_Xhi[BB * SEQ * EE];
__device__ __align__(16) __nv_bfloat16 g_Xlo[BB * SEQ * EE];
__device__ float g_biasv[4 * DDIM];   // 0=interior 1=i0 2=i1 3=tail

// ---------------- helpers ----------------
__device__ __forceinline__ uint32_t smem_u32(const void* p) {
    uint32_t a;
    asm("{ .reg .u64 t; cvta.to.shared.u64 t, %1; cvt.u32.u64 %0, t; }" : "=r"(a) : "l"(p));
    return a;
}
__device__ __forceinline__ void cp16(uint32_t dst, const void* src, int sz) {
    asm volatile("cp.async.cg.shared.global [%0], [%1], 16, %2;"
                 :: "r"(dst), "l"(src), "r"(sz) : "memory");
}
#define CP_COMMIT() asm volatile("cp.async.commit_group;" ::: "memory")
#define CP_WAIT2()  asm volatile("cp.async.wait_group 2;" ::: "memory")

#define LDSM4(r0, r1, r2, r3, ad) \
    asm volatile("ldmatrix.sync.aligned.m8n8.x4.shared.b16 {%0,%1,%2,%3}, [%4];" \
                 : "=r"(r0), "=r"(r1), "=r"(r2), "=r"(r3) : "r"(ad))

#define MMA16816(d, a, bq) \
    asm volatile("mma.sync.aligned.m16n8k16.row.col.f32.bf16.bf16.f32 " \
                 "{%0,%1,%2,%3}, {%4,%5,%6,%7}, {%8,%9}, {%0,%1,%2,%3};" \
                 : "+f"((d)[0]), "+f"((d)[1]), "+f"((d)[2]), "+f"((d)[3]) \
                 : "r"((a)[0]), "r"((a)[1]), "r"((a)[2]), "r"((a)[3]), \
                   "r"((bq)[0]), "r"((bq)[1]))

// ---------------- preprocessing ----------------
__global__ void preproc_kernel(
    const float* __restrict__ W1, const float* __restrict__ b1,
    const float* __restrict__ W2, const float* __restrict__ b2,
    const float* __restrict__ W3, const float* __restrict__ b3,
    const float* __restrict__ W4, const float* __restrict__ b4)
{
    int idx = blockIdx.x * blockDim.x + threadIdx.x;
    if (idx >= DE) return;
    int d = idx >> 8, e = idx & 255;
    float w1 = W1[idx];
    const float* p2 = W2 + (size_t)idx * 2;
    float w20 = p2[0], w21 = p2[1];
    const float* p3 = W3 + (size_t)idx * 3;
    float w30 = p3[0], w31 = p3[1], w32 = p3[2];
    const float* p4 = W4 + (size_t)idx * 4;
    float w40 = p4[0], w41 = p4[1], w42 = p4[2], w43 = p4[3];

    float tap[NTAPS];
    tap[0] = w40;                                         // interior, delta=-2
    tap[1] = w30 + w40 + w41;
    tap[2] = w1 + w20 + w30 + w31 + w40 + w41 + w42;
    tap[3] = w21 + w31 + w32 + w41 + w42 + w43;
    tap[4] = w32 + w42 + w43;
    tap[5] = w43;
    tap[6] = w1;                                          // tail (unigram)
    tap[7]  = w1 + w20 + w30 + w40;                       // i==0 taps x0..x3
    tap[8]  = w21 + w31 + w41;
    tap[9]  = w32 + w42;
    tap[10] = w43;
    tap[11] = w30 + w40;                                  // i==1 taps x0..x4
    tap[12] = w1 + w20 + w30 + w31 + w40 + w41;
    tap[13] = w21 + w31 + w32 + w41 + w42;
    tap[14] = w32 + w42 + w43;
    tap[15] = w43;
#pragma unroll
    for (int t = 0; t < NTAPS; ++t) {
        __nv_bfloat16 h = __float2bfloat16(tap[t]);
        g_Whi[(size_t)t * DE + idx] = h;
        g_Wlo[(size_t)t * DE + idx] = __float2bfloat16(tap[t] - __bfloat162float(h));
    }
    if (e == 0) {
        float B1 = b1[d], B2 = b2[d], B3 = b3[d], B4 = b4[d];
        g_biasv[0 * DDIM + d] = B1 + B2 + 2.f * B3 + 3.f * B4;
        g_biasv[1 * DDIM + d] = B1 + B2 + B3 + B4;
        g_biasv[2 * DDIM + d] = B1 + B2 + 2.f * B3 + 2.f * B4;
        g_biasv[3 * DDIM + d] = B1;
    }
}

__global__ void convx_kernel(const float* __restrict__ x)
{
    int i = blockIdx.x * blockDim.x + threadIdx.x;
    const int N4 = BB * SEQ * EE / 4;
    if (i >= N4) return;
    float4 v = reinterpret_cast<const float4*>(x)[i];
    __nv_bfloat16 h0 = __float2bfloat16(v.x), h1 = __float2bfloat16(v.y);
    __nv_bfloat16 h2 = __float2bfloat16(v.z), h3 = __float2bfloat16(v.w);
    __nv_bfloat162 H0, H1, L0, L1;
    H0.x = h0; H0.y = h1; H1.x = h2; H1.y = h3;
    L0.x = __float2bfloat16(v.x - __bfloat162float(h0));
    L0.y = __float2bfloat16(v.y - __bfloat162float(h1));
    L1.x = __float2bfloat16(v.z - __bfloat162float(h2));
    L1.y = __float2bfloat16(v.w - __bfloat162float(h3));
    reinterpret_cast<__nv_bfloat162*>(g_Xhi)[2 * i + 0] = H0;
    reinterpret_cast<__nv_bfloat162*>(g_Xhi)[2 * i + 1] = H1;
    reinterpret_cast<__nv_bfloat162*>(g_Xlo)[2 * i + 0] = L0;
    reinterpret_cast<__nv_bfloat162*>(g_Xlo)[2 * i + 1] = L1;
}

// ---------------- bf16 3-pass HMMA GEMM ----------------
// grid.x = 1032: [0,512) interior, [512,1024) tail, [1024,1032) boundary
#define ROWB 80                       // smem row stride (32 bf16 + 8 pad)
#define STAGEB (128 * ROWB * 2)       // A tile + B tile = 20480 B
#define NSTAGE 4
#define SMEM_GEMM (NSTAGE * STAGEB)   // 81920 B

__global__ void __launch_bounds__(256) gemm_kernel(float* __restrict__ out)
{
    extern __shared__ char smem[];
    const uint32_t sb = smem_u32(smem);
    const int tid = threadIdx.x;
    const int lane = tid & 31;
    const int warp = tid >> 5;
    const int wm = warp >> 1;          // 0..3 (M)
    const int wn = warp & 1;           // 0..1 (N)

    const int id = blockIdx.x;
    bool bdry = false;
    int T, tap0, bidx, b = 0, ibeg = 0, delta0 = 0, cls = 0, dn;
    if (id < 512) {
        b = id >> 3; int my = (id >> 2) & 1; dn = id & 3;
        T = 6; tap0 = 0; bidx = 0; ibeg = 2 + my * 126; delta0 = -2;
    } else if (id < 1024) {
        int q = id - 512;
        b = q >> 3; int my = (q >> 2) & 1; dn = q & 3;
        T = 1; tap0 = 6; bidx = 3; ibeg = 256 + my * 128; delta0 = 0;
    } else {
        int q = id - 1024;
        cls = q >> 2; dn = q & 3; bdry = true;
        T = 4 + cls; tap0 = 7 + 4 * cls; bidx = 1 + cls;
    }
    const int d0 = dn * 128;
    const int C = 3 * T * 8;           // chunks of K=32: 3 passes x T taps x 8 e-slices

    float acc[2][8][4];
#pragma unroll
    for (int mi = 0; mi < 2; ++mi)
#pragma unroll
        for (int nb = 0; nb < 8; ++nb)
#pragma unroll
            for (int q = 0; q < 4; ++q) acc[mi][nb][q] = 0.f;

    // ---- loader: chunk c into stage s ----
    auto load = [&](int c, int s) {
        int p = c / (T * 8);
        int r = c - p * T * 8;
        int t = r >> 3;
        int ec = (r & 7) * 32;
        const __nv_bfloat16* Asrc = (p == 1) ? g_Xlo : g_Xhi;
        const __nv_bfloat16* Bsrc = (p == 2) ? g_Wlo : g_Whi;
        uint32_t As = sb + (uint32_t)s * STAGEB;
        uint32_t Bs = As + 128 * ROWB;
#pragma unroll
        for (int j = 0; j < 2; ++j) {
            int q = tid + 256 * j;
            int row = q >> 2, c16 = q & 3;
            // A: row of the M-tile
            int arow = bdry ? (row < 64 ? row : 63) : row;
            long grow = bdry ? ((long)arow * SEQ + t)
                             : ((long)b * SEQ + ibeg + delta0 + t + row);
            int ok = (bdry && row >= 64) ? 0 : 16;
            cp16(As + (uint32_t)(row * ROWB + c16 * 16),
                 Asrc + grow * EE + ec + c16 * 8, ok);
            // B: row = n within d-tile
            cp16(Bs + (uint32_t)(row * ROWB + c16 * 16),
                 Bsrc + (size_t)(tap0 + t) * DE + (size_t)(d0 + row) * EE + ec + c16 * 8,
                 16);
        }
    };

    for (int s = 0; s < 3; ++s) { load(s, s); CP_COMMIT(); }

    for (int c = 0; c < C; ++c) {
        CP_WAIT2();
        __syncthreads();
        if (c + 3 < C) load(c + 3, (c + 3) & (NSTAGE - 1));
        CP_COMMIT();

        const uint32_t As = sb + (uint32_t)(c & (NSTAGE - 1)) * STAGEB;
        const uint32_t Bs = As + 128 * ROWB;
#pragma unroll
        for (int ks = 0; ks < 2; ++ks) {
            uint32_t a[2][4];
#pragma unroll
            for (int mi = 0; mi < 2; ++mi) {
                int rrow = 32 * wm + 16 * mi + (lane & 7) + ((lane >> 3) & 1) * 8;
                uint32_t ad = As + (uint32_t)(rrow * ROWB) + ks * 32 + ((lane >> 4) << 4);
                LDSM4(a[mi][0], a[mi][1], a[mi][2], a[mi][3], ad);
            }
            uint32_t bf[8][2];
#pragma unroll
            for (int nb2 = 0; nb2 < 4; ++nb2) {
                int nrow = 64 * wn + 16 * nb2 + (lane & 7) + ((lane >> 4) << 3);
                uint32_t ad = Bs + (uint32_t)(nrow * ROWB) + ks * 32 + (((lane >> 3) & 1) << 4);
                uint32_t r0, r1, r2, r3;
                LDSM4(r0, r1, r2, r3, ad);
                bf[2 * nb2][0] = r0; bf[2 * nb2][1] = r1;
                bf[2 * nb2 + 1][0] = r2; bf[2 * nb2 + 1][1] = r3;
            }
#pragma unroll
            for (int mi = 0; mi < 2; ++mi)
#pragma unroll
                for (int nb = 0; nb < 8; ++nb)
                    MMA16816(acc[mi][nb], a[mi], bf[nb]);
        }
    }

    // ---- epilogue ----
#pragma unroll
    for (int mi = 0; mi < 2; ++mi) {
#pragma unroll
        for (int nb = 0; nb < 8; ++nb) {
            int m0 = 32 * wm + 16 * mi + (lane >> 2);
            int n0 = 64 * wn + 8 * nb + (lane & 3) * 2;
            float2 bv = *reinterpret_cast<const float2*>(&g_biasv[bidx * DDIM + d0 + n0]);
#pragma unroll
            for (int h = 0; h < 2; ++h) {
                int m = m0 + 8 * h;
                bool valid = bdry ? (m < 64) : true;
                if (valid) {
                    long orow = bdry ? ((long)m * SEQ + cls)
                                     : ((long)b * SEQ + ibeg + m);
                    float2 v;
                    v.x = acc[mi][nb][2 * h + 0] + bv.x;
                    v.y = acc[mi][nb][2 * h + 1] + bv.y;
                    *reinterpret_cast<float2*>(&out[orow * DDIM + d0 + n0]) = v;
                }
            }
        }
    }
}

// ---------------- host ----------------
extern "C" void kernel_launch(void* const* d_in, const int* in_sizes, int n_in,
                              void* d_out, int out_size)
{
    (void)in_sizes; (void)n_in; (void)out_size;
    const float* x  = (const float*)d_in[0];
    const float* W1 = (const float*)d_in[1];
    const float* b1 = (const float*)d_in[2];
    const float* W2 = (const float*)d_in[3];
    const float* b2 = (const float*)d_in[4];
    const float* W3 = (const float*)d_in[5];
    const float* b3 = (const float*)d_in[6];
    const float* W4 = (const float*)d_in[7];
    const float* b4 = (const float*)d_in[8];
    float* out = (float*)d_out;

    preproc_kernel<<<(DE + 255) / 256, 256>>>(W1, b1, W2, b2, W3, b3, W4, b4);
    convx_kernel<<<(BB * SEQ * EE / 4 + 255) / 256, 256>>>(x);

    static bool attr_set = false;
    if (!attr_set) {
        cudaFuncSetAttribute(gemm_kernel,
                             cudaFuncAttributeMaxDynamicSharedMemorySize, SMEM_GEMM);
        attr_set = true;
    }
    gemm_kernel<<<1032, 256, SMEM_GEMM>>>(out);
}

// round 8
// speedup vs baseline: 3.6006x; 1.1625x over previous
#include <cuda_runtime.h>
#include <cuda_bf16.h>
#include <cstdint>
#include <cstddef>

#define BB 64
#define SEQ 512
#define EE 256
#define DDIM 512
#define NTAPS 16
#define DE (DDIM * EE)
#define THREADS 512

#define ROWB 80                       // smem row stride bytes (32 bf16 + pad), 16B-mult
#define AROWS 328
#define ABYTES (AROWS * ROWB)         // 26240 per half (hi|lo)
#define ABUF (2 * ABYTES)             // 52480 per ec buffer
#define BSTAGE (2 * 128 * ROWB)       // 20480 (hi+lo)
#define SMEM_GEMM (2 * ABUF + 4 * BSTAGE)   // 186880

__device__ __align__(16) __nv_bfloat16 g_Whi[NTAPS * DE];
__device__ __align__(16) __nv_bfloat16 g_Wlo[NTAPS * DE];
__device__ __align__(16) __nv_bfloat16 g_Xhi[BB * SEQ * EE];
__device__ __align__(16) __nv_bfloat16 g_Xlo[BB * SEQ * EE];
__device__ float g_biasv[4 * DDIM];   // 0=interior 1=i0 2=i1 3=tail

// ---------------- helpers ----------------
__device__ __forceinline__ uint32_t smem_u32(const void* p) {
    uint32_t a;
    asm("{ .reg .u64 t; cvta.to.shared.u64 t, %1; cvt.u32.u64 %0, t; }" : "=r"(a) : "l"(p));
    return a;
}
__device__ __forceinline__ void cp16(uint32_t dst, const void* src) {
    asm volatile("cp.async.cg.shared.global [%0], [%1], 16;"
                 :: "r"(dst), "l"(src) : "memory");
}
#define CP_COMMIT() asm volatile("cp.async.commit_group;" ::: "memory")

#define LDSM4(r0, r1, r2, r3, ad) \
    asm volatile("ldmatrix.sync.aligned.m8n8.x4.shared.b16 {%0,%1,%2,%3}, [%4];" \
                 : "=r"(r0), "=r"(r1), "=r"(r2), "=r"(r3) : "r"(ad))

#define MMA16816(d, a, bq) \
    asm volatile("mma.sync.aligned.m16n8k16.row.col.f32.bf16.bf16.f32 " \
                 "{%0,%1,%2,%3}, {%4,%5,%6,%7}, {%8,%9}, {%0,%1,%2,%3};" \
                 : "+f"((d)[0]), "+f"((d)[1]), "+f"((d)[2]), "+f"((d)[3]) \
                 : "r"((a)[0]), "r"((a)[1]), "r"((a)[2]), "r"((a)[3]), \
                   "r"((bq)[0]), "r"((bq)[1]))

// ---------------- preprocessing ----------------
__global__ void preproc_kernel(
    const float* __restrict__ W1, const float* __restrict__ b1,
    const float* __restrict__ W2, const float* __restrict__ b2,
    const float* __restrict__ W3, const float* __restrict__ b3,
    const float* __restrict__ W4, const float* __restrict__ b4)
{
    int idx = blockIdx.x * blockDim.x + threadIdx.x;
    if (idx >= DE) return;
    int d = idx >> 8, e = idx & 255;
    float w1 = W1[idx];
    const float* p2 = W2 + (size_t)idx * 2;
    float w20 = p2[0], w21 = p2[1];
    const float* p3 = W3 + (size_t)idx * 3;
    float w30 = p3[0], w31 = p3[1], w32 = p3[2];
    const float* p4 = W4 + (size_t)idx * 4;
    float w40 = p4[0], w41 = p4[1], w42 = p4[2], w43 = p4[3];

    float tap[NTAPS];
    tap[0] = w40;                                         // interior, delta=-2
    tap[1] = w30 + w40 + w41;
    tap[2] = w1 + w20 + w30 + w31 + w40 + w41 + w42;
    tap[3] = w21 + w31 + w32 + w41 + w42 + w43;
    tap[4] = w32 + w42 + w43;
    tap[5] = w43;
    tap[6] = w1;                                          // tail (unigram)
    tap[7]  = w1 + w20 + w30 + w40;                       // i==0 taps x0..x3
    tap[8]  = w21 + w31 + w41;
    tap[9]  = w32 + w42;
    tap[10] = w43;
    tap[11] = w30 + w40;                                  // i==1 taps x0..x4
    tap[12] = w1 + w20 + w30 + w31 + w40 + w41;
    tap[13] = w21 + w31 + w32 + w41 + w42;
    tap[14] = w32 + w42 + w43;
    tap[15] = w43;
#pragma unroll
    for (int t = 0; t < NTAPS; ++t) {
        __nv_bfloat16 h = __float2bfloat16(tap[t]);
        g_Whi[(size_t)t * DE + idx] = h;
        g_Wlo[(size_t)t * DE + idx] = __float2bfloat16(tap[t] - __bfloat162float(h));
    }
    if (e == 0) {
        float B1 = b1[d], B2 = b2[d], B3 = b3[d], B4 = b4[d];
        g_biasv[0 * DDIM + d] = B1 + B2 + 2.f * B3 + 3.f * B4;
        g_biasv[1 * DDIM + d] = B1 + B2 + B3 + B4;
        g_biasv[2 * DDIM + d] = B1 + B2 + 2.f * B3 + 2.f * B4;
        g_biasv[3 * DDIM + d] = B1;
    }
}

__global__ void convx_kernel(const float* __restrict__ x)
{
    int i = blockIdx.x * blockDim.x + threadIdx.x;
    const int N4 = BB * SEQ * EE / 4;
    if (i >= N4) return;
    float4 v = reinterpret_cast<const float4*>(x)[i];
    __nv_bfloat16 h0 = __float2bfloat16(v.x), h1 = __float2bfloat16(v.y);
    __nv_bfloat16 h2 = __float2bfloat16(v.z), h3 = __float2bfloat16(v.w);
    __nv_bfloat162 H0, H1, L0, L1;
    H0.x = h0; H0.y = h1; H1.x = h2; H1.y = h3;
    L0.x = __float2bfloat16(v.x - __bfloat162float(h0));
    L0.y = __float2bfloat16(v.y - __bfloat162float(h1));
    L1.x = __float2bfloat16(v.z - __bfloat162float(h2));
    L1.y = __float2bfloat16(v.w - __bfloat162float(h3));
    reinterpret_cast<__nv_bfloat162*>(g_Xhi)[2 * i + 0] = H0;
    reinterpret_cast<__nv_bfloat162*>(g_Xhi)[2 * i + 1] = H1;
    reinterpret_cast<__nv_bfloat162*>(g_Xlo)[2 * i + 0] = L0;
    reinterpret_cast<__nv_bfloat162*>(g_Xlo)[2 * i + 1] = L1;
}

// ---------------- bf16 3-pass HMMA GEMM, hoisted-A ----------------
// grid = 520: [0,256) interior (M=256 rows i=2..255+slop), [256,512) tail,
//             [512,520) boundary (batch-as-M, M=64)
__global__ void __launch_bounds__(THREADS, 1) gemm_kernel(float* __restrict__ out)
{
    extern __shared__ char smem[];
    const uint32_t sb = smem_u32(smem);
    const int tid = threadIdx.x;
    const int lane = tid & 31;
    const int warp = tid >> 5;
    const int wm = warp >> 1;          // 0..7
    const int wn = warp & 1;           // 0..1

    const int id = blockIdx.x;
    bool bdry = false;
    int T, tap0, bidx, b = 0, cls = 0, dn, abase = 0, obase = 0;
    if (id < 256) {
        b = id >> 2; dn = id & 3;
        T = 6; tap0 = 0; bidx = 0; abase = b * SEQ; obase = b * SEQ + 2;
    } else if (id < 512) {
        int q = id - 256; b = q >> 2; dn = q & 3;
        T = 1; tap0 = 6; bidx = 3; abase = b * SEQ + 256; obase = abase;
    } else {
        int q = id - 512; cls = q >> 2; dn = q & 3; bdry = true;
        T = 4 + cls; tap0 = 7 + 4 * cls; bidx = 1 + cls;
    }
    const int d0 = dn * 128;
    const int C = 8 * T;
    const int arows = bdry ? T * 64 : (T == 1 ? 256 : 261);
    const bool active = !bdry || (wm < 2);
    const bool late = (T < 3);

    // ---- loaders ----
    auto loadA = [&](int ec) {
        const uint32_t Ab = sb + (uint32_t)((ec & 1) * ABUF);
        const int ecol = ec * 32;
        const int nops = arows * 8;
        for (int q = tid; q < nops; q += THREADS) {
            int row = q >> 3, half = (q >> 2) & 1, c16 = q & 3;
            long gr = bdry ? ((long)(row & 63) * SEQ + (row >> 6))
                           : (long)(abase + row);
            const __nv_bfloat16* src =
                (half ? g_Xlo : g_Xhi) + gr * EE + ecol + c16 * 8;
            cp16(Ab + (uint32_t)(half * ABYTES + row * ROWB + c16 * 16), src);
        }
    };
    auto loadB = [&](int k) {
        const int ec = k / T, t = k - ec * T;
        const uint32_t Bs = sb + 2 * ABUF + (uint32_t)((k & 3) * BSTAGE);
        const size_t wbase = (size_t)(tap0 + t) * DE;
        const int ecol = ec * 32;
#pragma unroll
        for (int j = 0; j < 2; ++j) {
            int q = tid + THREADS * j;
            int row = q >> 3, half = (q >> 2) & 1, c16 = q & 3;
            const __nv_bfloat16* src =
                (half ? g_Wlo : g_Whi) + wbase + (size_t)(d0 + row) * EE + ecol + c16 * 8;
            cp16(Bs + (uint32_t)(half * 10240 + row * ROWB + c16 * 16), src);
        }
    };
    auto issue = [&](int k) {
        if (k % T == 0) loadA(k / T);
        loadB(k);
        CP_COMMIT();
    };

    float acc[2][8][4];
#pragma unroll
    for (int mi = 0; mi < 2; ++mi)
#pragma unroll
        for (int nb = 0; nb < 8; ++nb)
#pragma unroll
            for (int q = 0; q < 4; ++q) acc[mi][nb][q] = 0.f;

    int committed = 0;
    const int depth = late ? 2 : 3;
    for (int k = 0; k < depth; ++k) { issue(k); ++committed; }

    for (int k = 0; k < C; ++k) {
        const int n = committed - (k + 1);
        if (n == 0) asm volatile("cp.async.wait_group 0;" ::: "memory");
        else if (n == 1) asm volatile("cp.async.wait_group 1;" ::: "memory");
        else asm volatile("cp.async.wait_group 2;" ::: "memory");
        __syncthreads();
        if (!late && k + 3 < C) { issue(k + 3); ++committed; }

        const int ec = k / T, t = k - ec * T;
        const uint32_t Ab = sb + (uint32_t)((ec & 1) * ABUF)
                               + (uint32_t)((bdry ? t * 64 : t) * ROWB);
        const uint32_t Bs = sb + 2 * ABUF + (uint32_t)((k & 3) * BSTAGE);

        if (active) {
#pragma unroll
            for (int ks = 0; ks < 2; ++ks) {
                uint32_t ah[2][4], al[2][4];
#pragma unroll
                for (int mi = 0; mi < 2; ++mi) {
                    int rrow = 32 * wm + 16 * mi + (lane & 7) + ((lane >> 3) & 1) * 8;
                    uint32_t ad = Ab + (uint32_t)(rrow * ROWB) + ks * 32 + ((lane >> 4) << 4);
                    LDSM4(ah[mi][0], ah[mi][1], ah[mi][2], ah[mi][3], ad);
                    LDSM4(al[mi][0], al[mi][1], al[mi][2], al[mi][3], ad + ABYTES);
                }
                uint32_t bq[8][2];
#pragma unroll
                for (int nb2 = 0; nb2 < 4; ++nb2) {
                    int nrow = 64 * wn + 16 * nb2 + (lane & 7) + ((lane >> 4) << 3);
                    uint32_t ad = Bs + (uint32_t)(nrow * ROWB) + ks * 32 + (((lane >> 3) & 1) << 4);
                    uint32_t r0, r1, r2, r3;
                    LDSM4(r0, r1, r2, r3, ad);
                    bq[2 * nb2][0] = r0; bq[2 * nb2][1] = r1;
                    bq[2 * nb2 + 1][0] = r2; bq[2 * nb2 + 1][1] = r3;
                }
#pragma unroll
                for (int mi = 0; mi < 2; ++mi)
#pragma unroll
                    for (int nb = 0; nb < 8; ++nb) MMA16816(acc[mi][nb], ah[mi], bq[nb]);
#pragma unroll
                for (int mi = 0; mi < 2; ++mi)
#pragma unroll
                    for (int nb = 0; nb < 8; ++nb) MMA16816(acc[mi][nb], al[mi], bq[nb]);
                // reload B-lo fragments over bq
#pragma unroll
                for (int nb2 = 0; nb2 < 4; ++nb2) {
                    int nrow = 64 * wn + 16 * nb2 + (lane & 7) + ((lane >> 4) << 3);
                    uint32_t ad = Bs + 10240u + (uint32_t)(nrow * ROWB) + ks * 32 + (((lane >> 3) & 1) << 4);
                    uint32_t r0, r1, r2, r3;
                    LDSM4(r0, r1, r2, r3, ad);
                    bq[2 * nb2][0] = r0; bq[2 * nb2][1] = r1;
                    bq[2 * nb2 + 1][0] = r2; bq[2 * nb2 + 1][1] = r3;
                }
#pragma unroll
                for (int mi = 0; mi < 2; ++mi)
#pragma unroll
                    for (int nb = 0; nb < 8; ++nb) MMA16816(acc[mi][nb], ah[mi], bq[nb]);
            }
        }
        if (late && k + 2 < C) {
            __syncthreads();
            issue(k + 2); ++committed;
        }
    }

    // ---- epilogue ----
    if (active) {
#pragma unroll
        for (int mi = 0; mi < 2; ++mi) {
#pragma unroll
            for (int nb = 0; nb < 8; ++nb) {
                int m0 = 32 * wm + 16 * mi + (lane >> 2);
                int n0 = 64 * wn + 8 * nb + (lane & 3) * 2;
                float2 bv = *reinterpret_cast<const float2*>(&g_biasv[bidx * DDIM + d0 + n0]);
#pragma unroll
                for (int h = 0; h < 2; ++h) {
                    int m = m0 + 8 * h;
                    bool valid = bdry ? (m < 64) : (T == 6 ? (m < 254) : true);
                    if (valid) {
                        long orow = bdry ? ((long)m * SEQ + cls) : (long)(obase + m);
                        float2 v;
                        v.x = acc[mi][nb][2 * h + 0] + bv.x;
                        v.y = acc[mi][nb][2 * h + 1] + bv.y;
                        *reinterpret_cast<float2*>(&out[orow * DDIM + d0 + n0]) = v;
                    }
                }
            }
        }
    }
}

// ---------------- host ----------------
extern "C" void kernel_launch(void* const* d_in, const int* in_sizes, int n_in,
                              void* d_out, int out_size)
{
    (void)in_sizes; (void)n_in; (void)out_size;
    const float* x  = (const float*)d_in[0];
    const float* W1 = (const float*)d_in[1];
    const float* b1 = (const float*)d_in[2];
    const float* W2 = (const float*)d_in[3];
    const float* b2 = (const float*)d_in[4];
    const float* W3 = (const float*)d_in[5];
    const float* b3 = (const float*)d_in[6];
    const float* W4 = (const float*)d_in[7];
    const float* b4 = (const float*)d_in[8];
    float* out = (float*)d_out;

    preproc_kernel<<<(DE + 255) / 256, 256>>>(W1, b1, W2, b2, W3, b3, W4, b4);
    convx_kernel<<<(BB * SEQ * EE / 4 + 255) / 256, 256>>>(x);

    // unconditional (no static guard; cheap, capture-safe — not a stream op)
    cudaFuncSetAttribute(gemm_kernel,
                         cudaFuncAttributeMaxDynamicSharedMemorySize, SMEM_GEMM);
    gemm_kernel<<<520, THREADS, SMEM_GEMM>>>(out);
}

// round 10
// speedup vs baseline: 4.7303x; 1.3138x over previous
#include <cuda_runtime.h>
#include <cstdint>
#include <cstddef>

#define BB 64
#define SEQ 512
#define EE 256
#define DDIM 512
#define NTAPS 16
#define DE (DDIM * EE)
#define THREADS 256

#define ROWB 144                      // 32 floats + 16B pad
#define AROWS 328
#define ABUF (AROWS * ROWB)           // 47232 per ec buffer
#define BSTAGE (128 * ROWB)           // 18432
#define SMEM_GEMM (2 * ABUF + 4 * BSTAGE)   // 168192

__device__ __align__(16) float g_W[NTAPS * DE];   // tf32-rounded combined taps
__device__ float g_biasv[4 * DDIM];   // 0=interior 1=i0 2=i1 3=tail

// ---------------- helpers ----------------
__device__ __forceinline__ uint32_t smem_u32(const void* p) {
    uint32_t a;
    asm("{ .reg .u64 t; cvta.to.shared.u64 t, %1; cvt.u32.u64 %0, t; }" : "=r"(a) : "l"(p));
    return a;
}
__device__ __forceinline__ void cp16(uint32_t dst, const void* src) {
    asm volatile("cp.async.cg.shared.global [%0], [%1], 16;"
                 :: "r"(dst), "l"(src) : "memory");
}
#define CP_COMMIT() asm volatile("cp.async.commit_group;" ::: "memory")

#define LDSM4(r0, r1, r2, r3, ad) \
    asm volatile("ldmatrix.sync.aligned.m8n8.x4.shared.b16 {%0,%1,%2,%3}, [%4];" \
                 : "=r"(r0), "=r"(r1), "=r"(r2), "=r"(r3) : "r"(ad))

#define MMA_TF32(d, a, bq) \
    asm volatile("mma.sync.aligned.m16n8k8.row.col.f32.tf32.tf32.f32 " \
                 "{%0,%1,%2,%3}, {%4,%5,%6,%7}, {%8,%9}, {%0,%1,%2,%3};" \
                 : "+f"((d)[0]), "+f"((d)[1]), "+f"((d)[2]), "+f"((d)[3]) \
                 : "r"((a)[0]), "r"((a)[1]), "r"((a)[2]), "r"((a)[3]), \
                   "r"((bq)[0]), "r"((bq)[1]))

__device__ __forceinline__ uint32_t cvt_tf32(uint32_t raw) {
    uint32_t u;
    asm("cvt.rna.tf32.f32 %0, %1;" : "=r"(u) : "f"(__uint_as_float(raw)));
    return u;
}
__device__ __forceinline__ float round_tf32(float f) {
    uint32_t u;
    asm("cvt.rna.tf32.f32 %0, %1;" : "=r"(u) : "f"(f));
    return __uint_as_float(u);
}

// ---------------- preprocessing: combined taps, tf32-rounded ----------------
__global__ void preproc_kernel(
    const float* __restrict__ W1, const float* __restrict__ b1,
    const float* __restrict__ W2, const float* __restrict__ b2,
    const float* __restrict__ W3, const float* __restrict__ b3,
    const float* __restrict__ W4, const float* __restrict__ b4)
{
    int idx = blockIdx.x * blockDim.x + threadIdx.x;
    if (idx >= DE) return;
    int d = idx >> 8, e = idx & 255;
    float w1 = W1[idx];
    const float* p2 = W2 + (size_t)idx * 2;
    float w20 = p2[0], w21 = p2[1];
    const float* p3 = W3 + (size_t)idx * 3;
    float w30 = p3[0], w31 = p3[1], w32 = p3[2];
    const float* p4 = W4 + (size_t)idx * 4;
    float w40 = p4[0], w41 = p4[1], w42 = p4[2], w43 = p4[3];

    float tap[NTAPS];
    tap[0] = w40;                                         // interior, delta=-2
    tap[1] = w30 + w40 + w41;
    tap[2] = w1 + w20 + w30 + w31 + w40 + w41 + w42;
    tap[3] = w21 + w31 + w32 + w41 + w42 + w43;
    tap[4] = w32 + w42 + w43;
    tap[5] = w43;
    tap[6] = w1;                                          // tail (unigram)
    tap[7]  = w1 + w20 + w30 + w40;                       // i==0 taps x0..x3
    tap[8]  = w21 + w31 + w41;
    tap[9]  = w32 + w42;
    tap[10] = w43;
    tap[11] = w30 + w40;                                  // i==1 taps x0..x4
    tap[12] = w1 + w20 + w30 + w31 + w40 + w41;
    tap[13] = w21 + w31 + w32 + w41 + w42;
    tap[14] = w32 + w42 + w43;
    tap[15] = w43;
#pragma unroll
    for (int t = 0; t < NTAPS; ++t)
        g_W[(size_t)t * DE + idx] = round_tf32(tap[t]);
    if (e == 0) {
        float B1 = b1[d], B2 = b2[d], B3 = b3[d], B4 = b4[d];
        g_biasv[0 * DDIM + d] = B1 + B2 + 2.f * B3 + 3.f * B4;
        g_biasv[1 * DDIM + d] = B1 + B2 + B3 + B4;
        g_biasv[2 * DDIM + d] = B1 + B2 + 2.f * B3 + 2.f * B4;
        g_biasv[3 * DDIM + d] = B1;
    }
}

// ---------------- tf32 single-pass HMMA GEMM, hoisted-A ----------------
// grid = 520: [0,256) interior M=256 (i=2..255+slop) x N=128,
//             [256,512) tail, [512,520) boundary (batch-as-M, M=64)
// 256 threads = 8 warps (4 wm x 2 wn), warp tile 64x64.
__global__ void __launch_bounds__(THREADS, 1) gemm_kernel(
    const float* __restrict__ x, float* __restrict__ out)
{
    extern __shared__ char smem[];
    const uint32_t sb = smem_u32(smem);
    const int tid = threadIdx.x;
    const int lane = tid & 31;
    const int warp = tid >> 5;
    const int wm = warp >> 1;          // 0..3
    const int wn = warp & 1;           // 0..1
    const int rloc = lane & 7;
    const int sel = lane >> 3;         // 0..3

    const int id = blockIdx.x;
    bool bdry = false;
    int T, tap0, bidx, b = 0, cls = 0, dn, abase = 0, obase = 0;
    if (id < 256) {
        b = id >> 2; dn = id & 3;
        T = 6; tap0 = 0; bidx = 0; abase = b * SEQ; obase = b * SEQ + 2;
    } else if (id < 512) {
        int q = id - 256; b = q >> 2; dn = q & 3;
        T = 1; tap0 = 6; bidx = 3; abase = b * SEQ + 256; obase = abase;
    } else {
        int q = id - 512; cls = q >> 2; dn = q & 3; bdry = true;
        T = 4 + cls; tap0 = 7 + 4 * cls; bidx = 1 + cls;
    }
    const int d0 = dn * 128;
    const int C = 8 * T;
    const int arows = bdry ? T * 64 : (T == 1 ? 256 : 261);
    const bool active = !bdry || (wm == 0);
    const bool late = (T < 3);

    // ---- loaders ----
    auto loadA = [&](int ec) {
        const uint32_t Ab = sb + (uint32_t)((ec & 1) * ABUF);
        const int ecol = ec * 32;
        const int nops = arows * 8;
        for (int q = tid; q < nops; q += THREADS) {
            int row = q >> 3, seg = q & 7;
            long gr = bdry ? ((long)(row & 63) * SEQ + (row >> 6))
                           : (long)(abase + row);
            cp16(Ab + (uint32_t)(row * ROWB + seg * 16),
                 x + gr * EE + ecol + seg * 4);
        }
    };
    auto loadB = [&](int k) {
        const int ec = k / T, t = k - ec * T;
        const uint32_t Bs = sb + 2 * ABUF + (uint32_t)((k & 3) * BSTAGE);
        const float* wb = g_W + (size_t)(tap0 + t) * DE + (size_t)d0 * EE + ec * 32;
#pragma unroll
        for (int j = 0; j < 4; ++j) {
            int q = tid + THREADS * j;
            int row = q >> 3, seg = q & 7;
            cp16(Bs + (uint32_t)(row * ROWB + seg * 16),
                 wb + (size_t)row * EE + seg * 4);
        }
    };
    auto issue = [&](int k) {
        if (k % T == 0) loadA(k / T);
        loadB(k);
        CP_COMMIT();
    };

    float acc[4][8][4];
#pragma unroll
    for (int mi = 0; mi < 4; ++mi)
#pragma unroll
        for (int nb = 0; nb < 8; ++nb)
#pragma unroll
            for (int q = 0; q < 4; ++q) acc[mi][nb][q] = 0.f;

    int committed = 0;
    const int depth = late ? 2 : 3;
    for (int k = 0; k < depth; ++k) { issue(k); ++committed; }

    for (int k = 0; k < C; ++k) {
        const int n = committed - (k + 1);
        if (n == 0) asm volatile("cp.async.wait_group 0;" ::: "memory");
        else if (n == 1) asm volatile("cp.async.wait_group 1;" ::: "memory");
        else asm volatile("cp.async.wait_group 2;" ::: "memory");
        __syncthreads();
        if (!late && k + 3 < C) { issue(k + 3); ++committed; }

        const int ec = k / T, t = k - ec * T;
        const uint32_t Ab = sb + (uint32_t)((ec & 1) * ABUF)
                               + (uint32_t)((bdry ? t * 64 : t) * ROWB);
        const uint32_t Bs = sb + 2 * ABUF + (uint32_t)((k & 3) * BSTAGE);

        if (active) {
#pragma unroll
            for (int ks = 0; ks < 4; ++ks) {
                uint32_t a[4][4];
#pragma unroll
                for (int mi = 0; mi < 4; ++mi) {
                    int row = 64 * wm + 16 * mi + (sel & 1) * 8 + rloc;
                    uint32_t ad = Ab + (uint32_t)(row * ROWB)
                                     + (uint32_t)((ks * 8 + (sel >> 1) * 4) * 4);
                    LDSM4(a[mi][0], a[mi][1], a[mi][2], a[mi][3], ad);
                    a[mi][0] = cvt_tf32(a[mi][0]);
                    a[mi][1] = cvt_tf32(a[mi][1]);
                    a[mi][2] = cvt_tf32(a[mi][2]);
                    a[mi][3] = cvt_tf32(a[mi][3]);
                }
                uint32_t bq[8][2];
#pragma unroll
                for (int nbp = 0; nbp < 4; ++nbp) {
                    int nrow = 64 * wn + 16 * nbp + (sel >> 1) * 8 + rloc;
                    uint32_t ad = Bs + (uint32_t)(nrow * ROWB)
                                     + (uint32_t)((ks * 8 + (sel & 1) * 4) * 4);
                    uint32_t r0, r1, r2, r3;
                    LDSM4(r0, r1, r2, r3, ad);
                    bq[2 * nbp][0] = r0;     bq[2 * nbp][1] = r1;
                    bq[2 * nbp + 1][0] = r2; bq[2 * nbp + 1][1] = r3;
                }
#pragma unroll
                for (int mi = 0; mi < 4; ++mi)
#pragma unroll
                    for (int nb = 0; nb < 8; ++nb)
                        MMA_TF32(acc[mi][nb], a[mi], bq[nb]);
            }
        }
        if (late && k + 2 < C) {
            __syncthreads();
            issue(k + 2); ++committed;
        }
    }

    // ---- epilogue ----
    if (active) {
#pragma unroll
        for (int mi = 0; mi < 4; ++mi) {
#pragma unroll
            for (int nb = 0; nb < 8; ++nb) {
                int m0 = 64 * wm + 16 * mi + (lane >> 2);
                int n0 = 64 * wn + 8 * nb + (lane & 3) * 2;
                float2 bv = *reinterpret_cast<const float2*>(&g_biasv[bidx * DDIM + d0 + n0]);
#pragma unroll
                for (int h = 0; h < 2; ++h) {
                    int m = m0 + 8 * h;
                    bool valid = bdry ? (m < 64) : (T == 6 ? (m < 254) : true);
                    if (valid) {
                        long orow = bdry ? ((long)m * SEQ + cls) : (long)(obase + m);
                        float2 v;
                        v.x = acc[mi][nb][2 * h + 0] + bv.x;
                        v.y = acc[mi][nb][2 * h + 1] + bv.y;
                        *reinterpret_cast<float2*>(&out[orow * DDIM + d0 + n0]) = v;
                    }
                }
            }
        }
    }
}

// ---------------- host ----------------
extern "C" void kernel_launch(void* const* d_in, const int* in_sizes, int n_in,
                              void* d_out, int out_size)
{
    (void)in_sizes; (void)n_in; (void)out_size;
    const float* x  = (const float*)d_in[0];
    const float* W1 = (const float*)d_in[1];
    const float* b1 = (const float*)d_in[2];
    const float* W2 = (const float*)d_in[3];
    const float* b2 = (const float*)d_in[4];
    const float* W3 = (const float*)d_in[5];
    const float* b3 = (const float*)d_in[6];
    const float* W4 = (const float*)d_in[7];
    const float* b4 = (const float*)d_in[8];
    float* out = (float*)d_out;

    preproc_kernel<<<(DE + 255) / 256, 256>>>(W1, b1, W2, b2, W3, b3, W4, b4);

    cudaFuncSetAttribute(gemm_kernel,
                         cudaFuncAttributeMaxDynamicSharedMemorySize, SMEM_GEMM);
    gemm_kernel<<<520, THREADS, SMEM_GEMM>>>(x, out);
}

// round 11
// speedup vs baseline: 4.7797x; 1.0104x over previous
#include <cuda_runtime.h>
#include <cstdint>
#include <cstddef>

#define BB 64
#define SEQ 512
#define EE 256
#define DDIM 512
#define NTAPS 16
#define DE (DDIM * EE)
#define THREADS 512

#define ROWB 144                      // 32 floats + 16B pad
#define AROWS 328
#define ABUF (AROWS * ROWB)           // 47232 per ec buffer
#define BSTAGE (128 * ROWB)           // 18432
#define SMEM_GEMM (2 * ABUF + 4 * BSTAGE)   // 168192

__device__ __align__(16) float g_W[NTAPS * DE];       // tf32-rounded combined taps
__device__ __align__(16) float g_Xr[BB * SEQ * EE];   // tf32-rounded features
__device__ float g_biasv[4 * DDIM];   // 0=interior 1=i0 2=i1 3=tail

// ---------------- helpers ----------------
__device__ __forceinline__ uint32_t smem_u32(const void* p) {
    uint32_t a;
    asm("{ .reg .u64 t; cvta.to.shared.u64 t, %1; cvt.u32.u64 %0, t; }" : "=r"(a) : "l"(p));
    return a;
}
__device__ __forceinline__ void cp16(uint32_t dst, const void* src) {
    asm volatile("cp.async.cg.shared.global [%0], [%1], 16;"
                 :: "r"(dst), "l"(src) : "memory");
}
#define CP_COMMIT() asm volatile("cp.async.commit_group;" ::: "memory")

#define LDSM4(r0, r1, r2, r3, ad) \
    asm volatile("ldmatrix.sync.aligned.m8n8.x4.shared.b16 {%0,%1,%2,%3}, [%4];" \
                 : "=r"(r0), "=r"(r1), "=r"(r2), "=r"(r3) : "r"(ad))

#define MMA_TF32(d, a, bq) \
    asm volatile("mma.sync.aligned.m16n8k8.row.col.f32.tf32.tf32.f32 " \
                 "{%0,%1,%2,%3}, {%4,%5,%6,%7}, {%8,%9}, {%0,%1,%2,%3};" \
                 : "+f"((d)[0]), "+f"((d)[1]), "+f"((d)[2]), "+f"((d)[3]) \
                 : "r"((a)[0]), "r"((a)[1]), "r"((a)[2]), "r"((a)[3]), \
                   "r"((bq)[0]), "r"((bq)[1]))

__device__ __forceinline__ float round_tf32(float f) {
    uint32_t u;
    asm("cvt.rna.tf32.f32 %0, %1;" : "=r"(u) : "f"(f));
    return __uint_as_float(u);
}

// ---------------- preprocessing ----------------
__global__ void preproc_kernel(
    const float* __restrict__ W1, const float* __restrict__ b1,
    const float* __restrict__ W2, const float* __restrict__ b2,
    const float* __restrict__ W3, const float* __restrict__ b3,
    const float* __restrict__ W4, const float* __restrict__ b4)
{
    int idx = blockIdx.x * blockDim.x + threadIdx.x;
    if (idx >= DE) return;
    int d = idx >> 8, e = idx & 255;
    float w1 = W1[idx];
    const float* p2 = W2 + (size_t)idx * 2;
    float w20 = p2[0], w21 = p2[1];
    const float* p3 = W3 + (size_t)idx * 3;
    float w30 = p3[0], w31 = p3[1], w32 = p3[2];
    const float* p4 = W4 + (size_t)idx * 4;
    float w40 = p4[0], w41 = p4[1], w42 = p4[2], w43 = p4[3];

    float tap[NTAPS];
    tap[0] = w40;                                         // interior, delta=-2
    tap[1] = w30 + w40 + w41;
    tap[2] = w1 + w20 + w30 + w31 + w40 + w41 + w42;
    tap[3] = w21 + w31 + w32 + w41 + w42 + w43;
    tap[4] = w32 + w42 + w43;
    tap[5] = w43;
    tap[6] = w1;                                          // tail (unigram)
    tap[7]  = w1 + w20 + w30 + w40;                       // i==0 taps x0..x3
    tap[8]  = w21 + w31 + w41;
    tap[9]  = w32 + w42;
    tap[10] = w43;
    tap[11] = w30 + w40;                                  // i==1 taps x0..x4
    tap[12] = w1 + w20 + w30 + w31 + w40 + w41;
    tap[13] = w21 + w31 + w32 + w41 + w42;
    tap[14] = w32 + w42 + w43;
    tap[15] = w43;
#pragma unroll
    for (int t = 0; t < NTAPS; ++t)
        g_W[(size_t)t * DE + idx] = round_tf32(tap[t]);
    if (e == 0) {
        float B1 = b1[d], B2 = b2[d], B3 = b3[d], B4 = b4[d];
        g_biasv[0 * DDIM + d] = B1 + B2 + 2.f * B3 + 3.f * B4;
        g_biasv[1 * DDIM + d] = B1 + B2 + B3 + B4;
        g_biasv[2 * DDIM + d] = B1 + B2 + 2.f * B3 + 2.f * B4;
        g_biasv[3 * DDIM + d] = B1;
    }
}

// x -> tf32-rounded copy (removes cvt from gemm hot loop)
__global__ void prernd_kernel(const float* __restrict__ x)
{
    int i = blockIdx.x * blockDim.x + threadIdx.x;
    const int N4 = BB * SEQ * EE / 4;
    if (i >= N4) return;
    float4 v = reinterpret_cast<const float4*>(x)[i];
    v.x = round_tf32(v.x);
    v.y = round_tf32(v.y);
    v.z = round_tf32(v.z);
    v.w = round_tf32(v.w);
    reinterpret_cast<float4*>(g_Xr)[i] = v;
}

// ---------------- tf32 single-pass HMMA GEMM, hoisted-A, 16 warps ----------------
// grid = 520: [0,256) interior M=256 (i=2..255+slop) x N=128,
//             [256,512) tail, [512,520) boundary (batch-as-M, M=64)
// 512 threads = 16 warps (4 wm x 4 wn), warp tile 64x32.
__global__ void __launch_bounds__(THREADS, 1) gemm_kernel(float* __restrict__ out)
{
    extern __shared__ char smem[];
    const uint32_t sb = smem_u32(smem);
    const int tid = threadIdx.x;
    const int lane = tid & 31;
    const int warp = tid >> 5;
    const int wm = warp >> 2;          // 0..3
    const int wn = warp & 3;           // 0..3
    const int rloc = lane & 7;
    const int sel = lane >> 3;         // 0..3

    const int id = blockIdx.x;
    bool bdry = false;
    int T, tap0, bidx, b = 0, cls = 0, dn, abase = 0, obase = 0;
    if (id < 256) {
        b = id >> 2; dn = id & 3;
        T = 6; tap0 = 0; bidx = 0; abase = b * SEQ; obase = b * SEQ + 2;
    } else if (id < 512) {
        int q = id - 256; b = q >> 2; dn = q & 3;
        T = 1; tap0 = 6; bidx = 3; abase = b * SEQ + 256; obase = abase;
    } else {
        int q = id - 512; cls = q >> 2; dn = q & 3; bdry = true;
        T = 4 + cls; tap0 = 7 + 4 * cls; bidx = 1 + cls;
    }
    const int d0 = dn * 128;
    const int C = 8 * T;
    const int arows = bdry ? T * 64 : (T == 1 ? 256 : 261);
    const bool active = !bdry || (wm == 0);
    const bool late = (T < 3);

    // ---- loaders ----
    auto loadA = [&](int ec) {
        const uint32_t Ab = sb + (uint32_t)((ec & 1) * ABUF);
        const int ecol = ec * 32;
        const int nops = arows * 8;
        for (int q = tid; q < nops; q += THREADS) {
            int row = q >> 3, seg = q & 7;
            long gr = bdry ? ((long)(row & 63) * SEQ + (row >> 6))
                           : (long)(abase + row);
            cp16(Ab + (uint32_t)(row * ROWB + seg * 16),
                 g_Xr + gr * EE + ecol + seg * 4);
        }
    };
    auto loadB = [&](int k) {
        const int ec = k / T, t = k - ec * T;
        const uint32_t Bs = sb + 2 * ABUF + (uint32_t)((k & 3) * BSTAGE);
        const float* wb = g_W + (size_t)(tap0 + t) * DE + (size_t)d0 * EE + ec * 32;
#pragma unroll
        for (int j = 0; j < 2; ++j) {
            int q = tid + THREADS * j;
            int row = q >> 3, seg = q & 7;
            cp16(Bs + (uint32_t)(row * ROWB + seg * 16),
                 wb + (size_t)row * EE + seg * 4);
        }
    };
    auto issue = [&](int k) {
        if (k % T == 0) loadA(k / T);
        loadB(k);
        CP_COMMIT();
    };

    float acc[4][4][4];
#pragma unroll
    for (int mi = 0; mi < 4; ++mi)
#pragma unroll
        for (int nb = 0; nb < 4; ++nb)
#pragma unroll
            for (int q = 0; q < 4; ++q) acc[mi][nb][q] = 0.f;

    int committed = 0;
    const int depth = late ? 2 : 3;
    for (int k = 0; k < depth; ++k) { issue(k); ++committed; }

    for (int k = 0; k < C; ++k) {
        const int n = committed - (k + 1);
        if (n == 0) asm volatile("cp.async.wait_group 0;" ::: "memory");
        else if (n == 1) asm volatile("cp.async.wait_group 1;" ::: "memory");
        else asm volatile("cp.async.wait_group 2;" ::: "memory");
        __syncthreads();
        if (!late && k + 3 < C) { issue(k + 3); ++committed; }

        const int ec = k / T, t = k - ec * T;
        const uint32_t Ab = sb + (uint32_t)((ec & 1) * ABUF)
                               + (uint32_t)((bdry ? t * 64 : t) * ROWB);
        const uint32_t Bs = sb + 2 * ABUF + (uint32_t)((k & 3) * BSTAGE);

        if (active) {
#pragma unroll
            for (int ks = 0; ks < 4; ++ks) {
                uint32_t a[4][4];
#pragma unroll
                for (int mi = 0; mi < 4; ++mi) {
                    int row = 64 * wm + 16 * mi + (sel & 1) * 8 + rloc;
                    uint32_t ad = Ab + (uint32_t)(row * ROWB)
                                     + (uint32_t)((ks * 8 + (sel >> 1) * 4) * 4);
                    LDSM4(a[mi][0], a[mi][1], a[mi][2], a[mi][3], ad);
                }
                uint32_t bq[4][2];
#pragma unroll
                for (int nbp = 0; nbp < 2; ++nbp) {
                    int nrow = 32 * wn + 16 * nbp + (sel >> 1) * 8 + rloc;
                    uint32_t ad = Bs + (uint32_t)(nrow * ROWB)
                                     + (uint32_t)((ks * 8 + (sel & 1) * 4) * 4);
                    uint32_t r0, r1, r2, r3;
                    LDSM4(r0, r1, r2, r3, ad);
                    bq[2 * nbp][0] = r0;     bq[2 * nbp][1] = r1;
                    bq[2 * nbp + 1][0] = r2; bq[2 * nbp + 1][1] = r3;
                }
#pragma unroll
                for (int mi = 0; mi < 4; ++mi)
#pragma unroll
                    for (int nb = 0; nb < 4; ++nb)
                        MMA_TF32(acc[mi][nb], a[mi], bq[nb]);
            }
        }
        if (late && k + 2 < C) {
            __syncthreads();
            issue(k + 2); ++committed;
        }
    }

    // ---- epilogue ----
    if (active) {
#pragma unroll
        for (int mi = 0; mi < 4; ++mi) {
#pragma unroll
            for (int nb = 0; nb < 4; ++nb) {
                int m0 = 64 * wm + 16 * mi + (lane >> 2);
                int n0 = 32 * wn + 8 * nb + (lane & 3) * 2;
                float2 bv = *reinterpret_cast<const float2*>(&g_biasv[bidx * DDIM + d0 + n0]);
#pragma unroll
                for (int h = 0; h < 2; ++h) {
                    int m = m0 + 8 * h;
                    bool valid = bdry ? (m < 64) : (T == 6 ? (m < 254) : true);
                    if (valid) {
                        long orow = bdry ? ((long)m * SEQ + cls) : (long)(obase + m);
                        float2 v;
                        v.x = acc[mi][nb][2 * h + 0] + bv.x;
                        v.y = acc[mi][nb][2 * h + 1] + bv.y;
                        *reinterpret_cast<float2*>(&out[orow * DDIM + d0 + n0]) = v;
                    }
                }
            }
        }
    }
}

// ---------------- host ----------------
extern "C" void kernel_launch(void* const* d_in, const int* in_sizes, int n_in,
                              void* d_out, int out_size)
{
    (void)in_sizes; (void)n_in; (void)out_size;
    const float* x  = (const float*)d_in[0];
    const float* W1 = (const float*)d_in[1];
    const float* b1 = (const float*)d_in[2];
    const float* W2 = (const float*)d_in[3];
    const float* b2 = (const float*)d_in[4];
    const float* W3 = (const float*)d_in[5];
    const float* b3 = (const float*)d_in[6];
    const float* W4 = (const float*)d_in[7];
    const float* b4 = (const float*)d_in[8];
    float* out = (float*)d_out;

    preproc_kernel<<<(DE + 255) / 256, 256>>>(W1, b1, W2, b2, W3, b3, W4, b4);
    prernd_kernel<<<(BB * SEQ * EE / 4 + 255) / 256, 256>>>(x);

    cudaFuncSetAttribute(gemm_kernel,
                         cudaFuncAttributeMaxDynamicSharedMemorySize, SMEM_GEMM);
    gemm_kernel<<<520, THREADS, SMEM_GEMM>>>(out);
}

// round 12
// speedup vs baseline: 6.6130x; 1.3835x over previous
#include <cuda_runtime.h>
#include <cuda_fp16.h>
#include <cstdint>
#include <cstddef>

#define BB 64
#define SEQ 512
#define EE 256
#define DDIM 512
#define NTAPS 16
#define DE (DDIM * EE)
#define THREADS 512

#define ROWB 80                       // 32 fp16 (64B) + 16B pad
#define AROWS 328
#define ABUF (AROWS * ROWB)           // 26240 per ec buffer
#define BSTAGE (128 * ROWB)           // 10240
#define SMEM_GEMM (2 * ABUF + 4 * BSTAGE)   // 93440

__device__ __align__(16) __half g_Wh[NTAPS * DE];     // fp16 combined taps
__device__ __align__(16) __half g_Xh[BB * SEQ * EE];  // fp16 features
__device__ float g_biasv[4 * DDIM];   // 0=interior 1=i0 2=i1 3=tail

// ---------------- helpers ----------------
__device__ __forceinline__ uint32_t smem_u32(const void* p) {
    uint32_t a;
    asm("{ .reg .u64 t; cvta.to.shared.u64 t, %1; cvt.u32.u64 %0, t; }" : "=r"(a) : "l"(p));
    return a;
}
__device__ __forceinline__ void cp16(uint32_t dst, const void* src) {
    asm volatile("cp.async.cg.shared.global [%0], [%1], 16;"
                 :: "r"(dst), "l"(src) : "memory");
}
#define CP_COMMIT() asm volatile("cp.async.commit_group;" ::: "memory")

#define LDSM4(r0, r1, r2, r3, ad) \
    asm volatile("ldmatrix.sync.aligned.m8n8.x4.shared.b16 {%0,%1,%2,%3}, [%4];" \
                 : "=r"(r0), "=r"(r1), "=r"(r2), "=r"(r3) : "r"(ad))

#define MMA_F16(d, a, bq) \
    asm volatile("mma.sync.aligned.m16n8k16.row.col.f32.f16.f16.f32 " \
                 "{%0,%1,%2,%3}, {%4,%5,%6,%7}, {%8,%9}, {%0,%1,%2,%3};" \
                 : "+f"((d)[0]), "+f"((d)[1]), "+f"((d)[2]), "+f"((d)[3]) \
                 : "r"((a)[0]), "r"((a)[1]), "r"((a)[2]), "r"((a)[3]), \
                   "r"((bq)[0]), "r"((bq)[1]))

// ---------------- preprocessing ----------------
__global__ void preproc_kernel(
    const float* __restrict__ W1, const float* __restrict__ b1,
    const float* __restrict__ W2, const float* __restrict__ b2,
    const float* __restrict__ W3, const float* __restrict__ b3,
    const float* __restrict__ W4, const float* __restrict__ b4)
{
    int idx = blockIdx.x * blockDim.x + threadIdx.x;
    if (idx >= DE) return;
    int d = idx >> 8, e = idx & 255;
    float w1 = W1[idx];
    const float* p2 = W2 + (size_t)idx * 2;
    float w20 = p2[0], w21 = p2[1];
    const float* p3 = W3 + (size_t)idx * 3;
    float w30 = p3[0], w31 = p3[1], w32 = p3[2];
    const float* p4 = W4 + (size_t)idx * 4;
    float w40 = p4[0], w41 = p4[1], w42 = p4[2], w43 = p4[3];

    float tap[NTAPS];
    tap[0] = w40;                                         // interior, delta=-2
    tap[1] = w30 + w40 + w41;
    tap[2] = w1 + w20 + w30 + w31 + w40 + w41 + w42;
    tap[3] = w21 + w31 + w32 + w41 + w42 + w43;
    tap[4] = w32 + w42 + w43;
    tap[5] = w43;
    tap[6] = w1;                                          // tail (unigram)
    tap[7]  = w1 + w20 + w30 + w40;                       // i==0 taps x0..x3
    tap[8]  = w21 + w31 + w41;
    tap[9]  = w32 + w42;
    tap[10] = w43;
    tap[11] = w30 + w40;                                  // i==1 taps x0..x4
    tap[12] = w1 + w20 + w30 + w31 + w40 + w41;
    tap[13] = w21 + w31 + w32 + w41 + w42;
    tap[14] = w32 + w42 + w43;
    tap[15] = w43;
#pragma unroll
    for (int t = 0; t < NTAPS; ++t)
        g_Wh[(size_t)t * DE + idx] = __float2half(tap[t]);
    if (e == 0) {
        float B1 = b1[d], B2 = b2[d], B3 = b3[d], B4 = b4[d];
        g_biasv[0 * DDIM + d] = B1 + B2 + 2.f * B3 + 3.f * B4;
        g_biasv[1 * DDIM + d] = B1 + B2 + B3 + B4;
        g_biasv[2 * DDIM + d] = B1 + B2 + 2.f * B3 + 2.f * B4;
        g_biasv[3 * DDIM + d] = B1;
    }
}

// x -> fp16
__global__ void convx_kernel(const float* __restrict__ x)
{
    int i = blockIdx.x * blockDim.x + threadIdx.x;
    const int N4 = BB * SEQ * EE / 4;
    if (i >= N4) return;
    float4 v = reinterpret_cast<const float4*>(x)[i];
    __half2* H = reinterpret_cast<__half2*>(g_Xh);
    H[2 * i + 0] = __floats2half2_rn(v.x, v.y);
    H[2 * i + 1] = __floats2half2_rn(v.z, v.w);
}

// ---------------- fp16 single-pass HMMA GEMM, hoisted-A ----------------
// grid = 520: [0,256) interior M=256 (i=2..255+slop) x N=128,
//             [256,512) tail, [512,520) boundary (batch-as-M, M=64)
// 512 threads = 16 warps (8 wm x 2 wn), warp tile 32x64.
__global__ void __launch_bounds__(THREADS, 1) gemm_kernel(float* __restrict__ out)
{
    extern __shared__ char smem[];
    const uint32_t sb = smem_u32(smem);
    const int tid = threadIdx.x;
    const int lane = tid & 31;
    const int warp = tid >> 5;
    const int wm = warp >> 1;          // 0..7
    const int wn = warp & 1;           // 0..1

    const int id = blockIdx.x;
    bool bdry = false;
    int T, tap0, bidx, b = 0, cls = 0, dn, abase = 0, obase = 0;
    if (id < 256) {
        b = id >> 2; dn = id & 3;
        T = 6; tap0 = 0; bidx = 0; abase = b * SEQ; obase = b * SEQ + 2;
    } else if (id < 512) {
        int q = id - 256; b = q >> 2; dn = q & 3;
        T = 1; tap0 = 6; bidx = 3; abase = b * SEQ + 256; obase = abase;
    } else {
        int q = id - 512; cls = q >> 2; dn = q & 3; bdry = true;
        T = 4 + cls; tap0 = 7 + 4 * cls; bidx = 1 + cls;
    }
    const int d0 = dn * 128;
    const int C = 8 * T;
    const int arows = bdry ? T * 64 : (T == 1 ? 256 : 261);
    const bool active = !bdry || (wm < 2);
    const bool late = (T < 3);

    // ---- loaders ----
    auto loadA = [&](int ec) {
        const uint32_t Ab = sb + (uint32_t)((ec & 1) * ABUF);
        const int ecol = ec * 32;
        const int nops = arows * 4;
        for (int q = tid; q < nops; q += THREADS) {
            int row = q >> 2, seg = q & 3;
            long gr = bdry ? ((long)(row & 63) * SEQ + (row >> 6))
                           : (long)(abase + row);
            cp16(Ab + (uint32_t)(row * ROWB + seg * 16),
                 g_Xh + gr * EE + ecol + seg * 8);
        }
    };
    auto loadB = [&](int k) {
        const int ec = k / T, t = k - ec * T;
        const uint32_t Bs = sb + 2 * ABUF + (uint32_t)((k & 3) * BSTAGE);
        const __half* wb = g_Wh + (size_t)(tap0 + t) * DE + (size_t)d0 * EE + ec * 32;
        {
            int row = tid >> 2, seg = tid & 3;
            cp16(Bs + (uint32_t)(row * ROWB + seg * 16),
                 wb + (size_t)row * EE + seg * 8);
        }
    };
    auto issue = [&](int k) {
        if (k % T == 0) loadA(k / T);
        loadB(k);
        CP_COMMIT();
    };

    float acc[2][8][4];
#pragma unroll
    for (int mi = 0; mi < 2; ++mi)
#pragma unroll
        for (int nb = 0; nb < 8; ++nb)
#pragma unroll
            for (int q = 0; q < 4; ++q) acc[mi][nb][q] = 0.f;

    int committed = 0;
    const int depth = late ? 2 : 3;
    for (int k = 0; k < depth; ++k) { issue(k); ++committed; }

    for (int k = 0; k < C; ++k) {
        const int n = committed - (k + 1);
        if (n == 0) asm volatile("cp.async.wait_group 0;" ::: "memory");
        else if (n == 1) asm volatile("cp.async.wait_group 1;" ::: "memory");
        else asm volatile("cp.async.wait_group 2;" ::: "memory");
        __syncthreads();
        if (!late && k + 3 < C) { issue(k + 3); ++committed; }

        const int ec = k / T, t = k - ec * T;
        const uint32_t Ab = sb + (uint32_t)((ec & 1) * ABUF)
                               + (uint32_t)((bdry ? t * 64 : t) * ROWB);
        const uint32_t Bs = sb + 2 * ABUF + (uint32_t)((k & 3) * BSTAGE);

        if (active) {
#pragma unroll
            for (int ks = 0; ks < 2; ++ks) {
                uint32_t a[2][4];
#pragma unroll
                for (int mi = 0; mi < 2; ++mi) {
                    int rrow = 32 * wm + 16 * mi + (lane & 7) + ((lane >> 3) & 1) * 8;
                    uint32_t ad = Ab + (uint32_t)(rrow * ROWB) + ks * 32 + ((lane >> 4) << 4);
                    LDSM4(a[mi][0], a[mi][1], a[mi][2], a[mi][3], ad);
                }
                uint32_t bq[8][2];
#pragma unroll
                for (int nb2 = 0; nb2 < 4; ++nb2) {
                    int nrow = 64 * wn + 16 * nb2 + (lane & 7) + ((lane >> 4) << 3);
                    uint32_t ad = Bs + (uint32_t)(nrow * ROWB) + ks * 32 + (((lane >> 3) & 1) << 4);
                    uint32_t r0, r1, r2, r3;
                    LDSM4(r0, r1, r2, r3, ad);
                    bq[2 * nb2][0] = r0;     bq[2 * nb2][1] = r1;
                    bq[2 * nb2 + 1][0] = r2; bq[2 * nb2 + 1][1] = r3;
                }
#pragma unroll
                for (int mi = 0; mi < 2; ++mi)
#pragma unroll
                    for (int nb = 0; nb < 8; ++nb)
                        MMA_F16(acc[mi][nb], a[mi], bq[nb]);
            }
        }
        if (late && k + 2 < C) {
            __syncthreads();
            issue(k + 2); ++committed;
        }
    }

    // ---- epilogue ----
    if (active) {
#pragma unroll
        for (int mi = 0; mi < 2; ++mi) {
#pragma unroll
            for (int nb = 0; nb < 8; ++nb) {
                int m0 = 32 * wm + 16 * mi + (lane >> 2);
                int n0 = 64 * wn + 8 * nb + (lane & 3) * 2;
                float2 bv = *reinterpret_cast<const float2*>(&g_biasv[bidx * DDIM + d0 + n0]);
#pragma unroll
                for (int h = 0; h < 2; ++h) {
                    int m = m0 + 8 * h;
                    bool valid = bdry ? (m < 64) : (T == 6 ? (m < 254) : true);
                    if (valid) {
                        long orow = bdry ? ((long)m * SEQ + cls) : (long)(obase + m);
                        float2 v;
                        v.x = acc[mi][nb][2 * h + 0] + bv.x;
                        v.y = acc[mi][nb][2 * h + 1] + bv.y;
                        *reinterpret_cast<float2*>(&out[orow * DDIM + d0 + n0]) = v;
                    }
                }
            }
        }
    }
}

// ---------------- host ----------------
extern "C" void kernel_launch(void* const* d_in, const int* in_sizes, int n_in,
                              void* d_out, int out_size)
{
    (void)in_sizes; (void)n_in; (void)out_size;
    const float* x  = (const float*)d_in[0];
    const float* W1 = (const float*)d_in[1];
    const float* b1 = (const float*)d_in[2];
    const float* W2 = (const float*)d_in[3];
    const float* b2 = (const float*)d_in[4];
    const float* W3 = (const float*)d_in[5];
    const float* b3 = (const float*)d_in[6];
    const float* W4 = (const float*)d_in[7];
    const float* b4 = (const float*)d_in[8];
    float* out = (float*)d_out;

    preproc_kernel<<<(DE + 255) / 256, 256>>>(W1, b1, W2, b2, W3, b3, W4, b4);
    convx_kernel<<<(BB * SEQ * EE / 4 + 255) / 256, 256>>>(x);

    cudaFuncSetAttribute(gemm_kernel,
                         cudaFuncAttributeMaxDynamicSharedMemorySize, SMEM_GEMM);
    gemm_kernel<<<520, THREADS, SMEM_GEMM>>>(out);
}